// round 3
// baseline (speedup 1.0000x reference)
#include <cuda_runtime.h>
#include <cuda_bf16.h>

// Problem constants
#define DIM 256
#define NATOMS 512
#define NCOLS 65536

// ---------------- device scratch (no allocation allowed) ----------------
__device__ float g_G[DIM * DIM];        // Gram matrix G = D D^T  (256x256)
__device__ float g_Ainv[128 * 128];
__device__ float g_T[128 * 128];        // T = Ainv * B
__device__ float g_S[128 * 128];        // Schur complement
__device__ float g_Sinv[128 * 128];
__device__ float g_M12[128 * 128];
__device__ float g_M11[128 * 128];
__device__ float g_Minv[DIM * DIM];     // G^{-1} (256x256)
__device__ float g_Dt[DIM * NATOMS];    // D (= dictionary^T), [256][512]
__device__ float g_W[DIM * NATOMS];     // W = G^{-1} D, [256][512]

// ---------------- 1) Gram: G[i][j] = sum_a dict[a][i]*dict[a][j] ----------------
// 32 blocks x 8 rows each, 256 threads (j)
__global__ void gram_kernel(const float* __restrict__ dict) {
    __shared__ float cols[8][NATOMS];   // 16 KB
    int i0 = blockIdx.x * 8;
    for (int t = threadIdx.x; t < 8 * NATOMS; t += 256) {
        int r = t >> 9;
        int a = t & 511;
        cols[r][a] = dict[a * DIM + i0 + r];
    }
    __syncthreads();
    int j = threadIdx.x;
    float s[8];
#pragma unroll
    for (int r = 0; r < 8; ++r) s[r] = 0.0f;
    for (int a = 0; a < NATOMS; ++a) {
        float dj = dict[a * DIM + j];
#pragma unroll
        for (int r = 0; r < 8; ++r) s[r] += cols[r][a] * dj;
    }
#pragma unroll
    for (int r = 0; r < 8; ++r) g_G[(i0 + r) * DIM + j] = s[r];
}

// ---------------- 2) 128x128 in-place Gauss-Jordan inverse (register resident) ----
// single block, 1024 threads: row = tid/8, 16-col segment per thread.
// which==0 : invert A = g_G[0:128,0:128] (lds=DIM)  -> g_Ainv
// which==1 : invert S = g_S (lds=128)               -> g_Sinv
// NOTE: src/dst selected in DEVICE code — __device__ symbols must never be
// passed as host-side kernel arguments (that was the R1 bug).
__global__ void inv128_kernel(int which) {
    const float* src = (which == 0) ? g_G : g_S;
    float* dst       = (which == 0) ? g_Ainv : g_Sinv;
    int lds          = (which == 0) ? DIM : 128;

    __shared__ float sh_col[128];
    __shared__ float sh_row[128];
    int tid = threadIdx.x;
    int row = tid >> 3;
    int seg = (tid & 7) << 4;   // column base of this thread's 16-wide segment
    float a[16];
#pragma unroll
    for (int c = 0; c < 16; ++c) a[c] = src[row * lds + seg + c];

    for (int k = 0; k < 128; ++k) {
        // publish column k (current values) : A[row][k]
#pragma unroll
        for (int c = 0; c < 16; ++c)
            if (seg + c == k) sh_col[row] = a[c];
        __syncthreads();
        float p = 1.0f / sh_col[k];      // 1 / A[k][k]
        float f = sh_col[row];           // current A[row][k]
        if (row == k) {
#pragma unroll
            for (int c = 0; c < 16; ++c) {
                int j = seg + c;
                float v = (j == k) ? p : a[c] * p;
                a[c] = v;
                sh_row[j] = v;
            }
        }
        __syncthreads();
        if (row != k) {
#pragma unroll
            for (int c = 0; c < 16; ++c) {
                int j = seg + c;
                a[c] = (j == k) ? (-f * p) : (a[c] - f * sh_row[j]);
            }
        }
        __syncthreads();
    }
#pragma unroll
    for (int c = 0; c < 16; ++c) dst[row * 128 + seg + c] = a[c];
}

// ---------------- 3) small 128^3 matmuls for Schur assembly -------------------
// T = Ainv * B   where B[k][j] = G[k][128+j]
__global__ void kT_kernel() {
    __shared__ float arow[128];
    int i = blockIdx.x;
    int j = threadIdx.x;
    arow[j] = g_Ainv[i * 128 + j];
    __syncthreads();
    float s = 0.0f;
#pragma unroll 8
    for (int k = 0; k < 128; ++k) s += arow[k] * g_G[k * DIM + 128 + j];
    g_T[i * 128 + j] = s;
}

// S[i][j] = C[i][j] - sum_k B[k][i]*T[k][j],  C[i][j] = G[128+i][128+j]
__global__ void kS_kernel() {
    __shared__ float bcol[128];
    int i = blockIdx.x;
    int j = threadIdx.x;
    bcol[j] = g_G[j * DIM + 128 + i];    // B[j][i] (j used as k-index loader)
    __syncthreads();
    float s = g_G[(128 + i) * DIM + 128 + j];
#pragma unroll 8
    for (int k = 0; k < 128; ++k) s -= bcol[k] * g_T[k * 128 + j];
    g_S[i * 128 + j] = s;
}

// M12 = -T * Sinv
__global__ void kM12_kernel() {
    __shared__ float trow[128];
    int i = blockIdx.x;
    int j = threadIdx.x;
    trow[j] = g_T[i * 128 + j];
    __syncthreads();
    float s = 0.0f;
#pragma unroll 8
    for (int k = 0; k < 128; ++k) s += trow[k] * g_Sinv[k * 128 + j];
    g_M12[i * 128 + j] = -s;
}

// M11 = Ainv - M12 * T^T  -> M11[i][j] = Ainv[i][j] - sum_k M12[i][k]*T[j][k]
__global__ void kM11_kernel() {
    __shared__ float m12row[128];
    int i = blockIdx.x;
    int j = threadIdx.x;
    m12row[j] = g_M12[i * 128 + j];
    __syncthreads();
    float s = g_Ainv[i * 128 + j];
#pragma unroll 8
    for (int k = 0; k < 128; ++k) s -= m12row[k] * g_T[j * 128 + k];
    g_M11[i * 128 + j] = s;
}

// assemble Minv from quadrants
__global__ void assemble_kernel() {
    int i = blockIdx.x;
    int j = threadIdx.x;
    float v;
    if (i < 128) {
        v = (j < 128) ? g_M11[i * 128 + j] : g_M12[i * 128 + (j - 128)];
    } else {
        v = (j < 128) ? g_M12[j * 128 + (i - 128)] : g_Sinv[(i - 128) * 128 + (j - 128)];
    }
    g_Minv[i * DIM + j] = v;
}

// ---------------- 4) transpose dictionary [512][256] -> Dt [256][512] ----------
__global__ void transpose_kernel(const float* __restrict__ dict) {
    __shared__ float t[32][33];
    int bx = blockIdx.x;   // 8 tiles along i (DIM)
    int by = blockIdx.y;   // 16 tiles along k (NATOMS)
    int x = bx * 32 + threadIdx.x;          // i
#pragma unroll
    for (int r = 0; r < 32; r += 8) {
        int k = by * 32 + threadIdx.y + r;
        t[threadIdx.y + r][threadIdx.x] = dict[k * DIM + x];
    }
    __syncthreads();
#pragma unroll
    for (int r = 0; r < 32; r += 8) {
        int i = bx * 32 + threadIdx.y + r;
        g_Dt[i * NATOMS + by * 32 + threadIdx.x] = t[threadIdx.x][threadIdx.y + r];
    }
}

// ---------------- 5) W = Minv * Dt  (256x256 x 256x512) ------------------------
// 32 blocks x 8 rows, 512 threads (k)
__global__ void w_kernel() {
    __shared__ float mrow[8][DIM];       // 8 KB
    int j0 = blockIdx.x * 8;
    for (int t = threadIdx.x; t < 8 * DIM; t += 512) {
        mrow[t >> 8][t & 255] = g_Minv[(j0 + (t >> 8)) * DIM + (t & 255)];
    }
    __syncthreads();
    int k = threadIdx.x;
    float s[8];
#pragma unroll
    for (int r = 0; r < 8; ++r) s[r] = 0.0f;
    for (int i = 0; i < DIM; ++i) {
        float dv = g_Dt[i * NATOMS + k];
#pragma unroll
        for (int r = 0; r < 8; ++r) s[r] += mrow[r][i] * dv;
    }
#pragma unroll
    for (int r = 0; r < 8; ++r) g_W[(j0 + r) * NATOMS + k] = s[r];
}

// ---------------- 6) big GEMM: out[n][k] = sum_j X[j][n] * W[j][k] -------------
// out: [65536, 512]. Block tile 128(n) x 128(k), K-chunk 16, 256 threads, 8x8/thread.
#define BM 128
#define BN 128
#define BK 16
__global__ __launch_bounds__(256, 2) void gemm_kernel(const float* __restrict__ X,
                                                      float* __restrict__ out) {
    __shared__ float As[BK][BM];   // A = X^T tile: As[kk][n]
    __shared__ float Bs[BK][BN];   // B = W tile:   Bs[kk][k]
    int n0 = blockIdx.x * BM;
    int k0 = blockIdx.y * BN;
    int tid = threadIdx.x;
    int tx = tid & 15;             // 0..15 -> 8 cols each
    int ty = tid >> 4;             // 0..15 -> 8 rows each

    float acc[8][8];
#pragma unroll
    for (int i = 0; i < 8; ++i)
#pragma unroll
        for (int u = 0; u < 8; ++u) acc[i][u] = 0.0f;

    int lkk = tid >> 4;            // 0..15 (row of tile to load)
    int lnn = (tid & 15) << 3;     // 0..120 (8-float segment)

    for (int j0 = 0; j0 < DIM; j0 += BK) {
        // load A tile: X[(j0+lkk)][n0+lnn .. +7]  (coalesced)
        const float4* sa = reinterpret_cast<const float4*>(&X[(size_t)(j0 + lkk) * NCOLS + n0 + lnn]);
        float4 a0 = sa[0], a1 = sa[1];
        *reinterpret_cast<float4*>(&As[lkk][lnn]) = a0;
        *reinterpret_cast<float4*>(&As[lkk][lnn + 4]) = a1;
        // load B tile: g_W[(j0+lkk)][k0+lnn .. +7]
        const float4* sb = reinterpret_cast<const float4*>(&g_W[(j0 + lkk) * NATOMS + k0 + lnn]);
        float4 b0 = sb[0], b1 = sb[1];
        *reinterpret_cast<float4*>(&Bs[lkk][lnn]) = b0;
        *reinterpret_cast<float4*>(&Bs[lkk][lnn + 4]) = b1;
        __syncthreads();

#pragma unroll
        for (int kk = 0; kk < BK; ++kk) {
            float a[8], b[8];
            float4 va0 = *reinterpret_cast<const float4*>(&As[kk][ty * 8]);
            float4 va1 = *reinterpret_cast<const float4*>(&As[kk][ty * 8 + 4]);
            float4 vb0 = *reinterpret_cast<const float4*>(&Bs[kk][tx * 8]);
            float4 vb1 = *reinterpret_cast<const float4*>(&Bs[kk][tx * 8 + 4]);
            a[0] = va0.x; a[1] = va0.y; a[2] = va0.z; a[3] = va0.w;
            a[4] = va1.x; a[5] = va1.y; a[6] = va1.z; a[7] = va1.w;
            b[0] = vb0.x; b[1] = vb0.y; b[2] = vb0.z; b[3] = vb0.w;
            b[4] = vb1.x; b[5] = vb1.y; b[6] = vb1.z; b[7] = vb1.w;
#pragma unroll
            for (int i = 0; i < 8; ++i)
#pragma unroll
                for (int u = 0; u < 8; ++u) acc[i][u] += a[i] * b[u];
        }
        __syncthreads();
    }

#pragma unroll
    for (int i = 0; i < 8; ++i) {
        size_t roff = (size_t)(n0 + ty * 8 + i) * NATOMS + k0 + tx * 8;
        float4* dst = reinterpret_cast<float4*>(&out[roff]);
        dst[0] = make_float4(acc[i][0], acc[i][1], acc[i][2], acc[i][3]);
        dst[1] = make_float4(acc[i][4], acc[i][5], acc[i][6], acc[i][7]);
    }
}

// ---------------- launch --------------------------------------------------------
extern "C" void kernel_launch(void* const* d_in, const int* in_sizes, int n_in,
                              void* d_out, int out_size) {
    // identify inputs by size for robustness
    const float* z_e  = (const float*)d_in[0];
    const float* dict = (const float*)d_in[1];
    if (in_sizes[0] == NATOMS * DIM && in_sizes[1] == DIM * NCOLS) {
        dict = (const float*)d_in[0];
        z_e  = (const float*)d_in[1];
    }
    float* out = (float*)d_out;

    gram_kernel<<<32, 256>>>(dict);
    inv128_kernel<<<1, 1024>>>(0);   // g_G[0:128,0:128] -> g_Ainv
    kT_kernel<<<128, 128>>>();
    kS_kernel<<<128, 128>>>();
    inv128_kernel<<<1, 1024>>>(1);   // g_S -> g_Sinv
    kM12_kernel<<<128, 128>>>();
    kM11_kernel<<<128, 128>>>();
    assemble_kernel<<<DIM, DIM>>>();
    transpose_kernel<<<dim3(8, 16), dim3(32, 8)>>>(dict);
    w_kernel<<<32, 512>>>();
    gemm_kernel<<<dim3(NCOLS / BM, NATOMS / BN), 256>>>(z_e, out);
}

// round 6
// speedup vs baseline: 1.2496x; 1.2496x over previous
#include <cuda_runtime.h>
#include <cuda_bf16.h>
#include <cstdint>

// Problem constants
#define DIM 256
#define NATOMS 512
#define NCOLS 65536

// ---------------- device scratch (no allocation allowed) ----------------
__device__ float g_G[DIM * DIM];        // Gram matrix G = D D^T  (256x256)
__device__ float g_Ainv[128 * 128];
__device__ float g_T[128 * 128];        // T = Ainv * B
__device__ float g_S[128 * 128];        // Schur complement
__device__ float g_Sinv[128 * 128];
__device__ float g_M12[128 * 128];
__device__ float g_M11[128 * 128];
__device__ float g_Minv[DIM * DIM];     // G^{-1} (256x256)
__device__ float g_Dt[DIM * NATOMS];    // D (= dictionary^T), [256][512]
__device__ float g_W[DIM * NATOMS];     // W = G^{-1} D, [256][512]

// bf16 split operands (16-byte aligned for cp.async 16B)
__device__ __align__(16) __nv_bfloat16 g_Xt_hi[(size_t)NCOLS * DIM];  // [m][k]
__device__ __align__(16) __nv_bfloat16 g_Xt_lo[(size_t)NCOLS * DIM];
__device__ __align__(16) __nv_bfloat16 g_Wt_hi[NATOMS * DIM];         // [n][k]
__device__ __align__(16) __nv_bfloat16 g_Wt_lo[NATOMS * DIM];

// ================= helpers (family-portable PTX only) =================
__device__ __forceinline__ uint32_t smem_u32(const void* p) {
    uint32_t a;
    asm("{ .reg .u64 t; cvta.to.shared.u64 t, %1; cvt.u32.u64 %0, t; }" : "=r"(a) : "l"(p));
    return a;
}
__device__ __forceinline__ uint32_t lds32(uint32_t addr) {
    uint32_t v;
    asm volatile("ld.shared.b32 %0, [%1];" : "=r"(v) : "r"(addr));
    return v;
}
__device__ __forceinline__ void cp_async16(uint32_t smem_addr, const void* gptr) {
    asm volatile("cp.async.cg.shared.global [%0], [%1], 16;" :: "r"(smem_addr), "l"(gptr));
}
__device__ __forceinline__ void cp_commit() {
    asm volatile("cp.async.commit_group;" ::: "memory");
}
__device__ __forceinline__ void cp_wait1() {
    asm volatile("cp.async.wait_group 1;" ::: "memory");
}
__device__ __forceinline__ void cp_wait0() {
    asm volatile("cp.async.wait_group 0;" ::: "memory");
}
__device__ __forceinline__ void mma16816(float* d, uint32_t a0, uint32_t a1, uint32_t a2,
                                         uint32_t a3, uint32_t b0, uint32_t b1) {
    asm volatile(
        "mma.sync.aligned.m16n8k16.row.col.f32.bf16.bf16.f32 "
        "{%0,%1,%2,%3}, {%4,%5,%6,%7}, {%8,%9}, {%0,%1,%2,%3};"
        : "+f"(d[0]), "+f"(d[1]), "+f"(d[2]), "+f"(d[3])
        : "r"(a0), "r"(a1), "r"(a2), "r"(a3), "r"(b0), "r"(b1));
}

// ---------------- 1) Gram: G[i][j] = sum_a dict[a][i]*dict[a][j] ----------------
__global__ void gram_kernel(const float* __restrict__ dict) {
    __shared__ float cols[8][NATOMS];
    int i0 = blockIdx.x * 8;
    for (int t = threadIdx.x; t < 8 * NATOMS; t += 256) {
        int r = t >> 9;
        int a = t & 511;
        cols[r][a] = dict[a * DIM + i0 + r];
    }
    __syncthreads();
    int j = threadIdx.x;
    float s[8];
#pragma unroll
    for (int r = 0; r < 8; ++r) s[r] = 0.0f;
    for (int a = 0; a < NATOMS; ++a) {
        float dj = dict[a * DIM + j];
#pragma unroll
        for (int r = 0; r < 8; ++r) s[r] += cols[r][a] * dj;
    }
#pragma unroll
    for (int r = 0; r < 8; ++r) g_G[(i0 + r) * DIM + j] = s[r];
}

// ---------------- 2) 128x128 register-resident Gauss-Jordan inverse ------------
__global__ void inv128_kernel(int which) {
    const float* src = (which == 0) ? g_G : g_S;
    float* dst       = (which == 0) ? g_Ainv : g_Sinv;
    int lds          = (which == 0) ? DIM : 128;

    __shared__ float sh_col[128];
    __shared__ float sh_row[128];
    int tid = threadIdx.x;
    int row = tid >> 3;
    int seg = (tid & 7) << 4;
    float a[16];
#pragma unroll
    for (int c = 0; c < 16; ++c) a[c] = src[row * lds + seg + c];

    for (int k = 0; k < 128; ++k) {
#pragma unroll
        for (int c = 0; c < 16; ++c)
            if (seg + c == k) sh_col[row] = a[c];
        __syncthreads();
        float p = 1.0f / sh_col[k];
        float f = sh_col[row];
        if (row == k) {
#pragma unroll
            for (int c = 0; c < 16; ++c) {
                int j = seg + c;
                float v = (j == k) ? p : a[c] * p;
                a[c] = v;
                sh_row[j] = v;
            }
        }
        __syncthreads();
        if (row != k) {
#pragma unroll
            for (int c = 0; c < 16; ++c) {
                int j = seg + c;
                a[c] = (j == k) ? (-f * p) : (a[c] - f * sh_row[j]);
            }
        }
        __syncthreads();
    }
#pragma unroll
    for (int c = 0; c < 16; ++c) dst[row * 128 + seg + c] = a[c];
}

// ---------------- 3) Schur assembly matmuls -----------------------------------
__global__ void kT_kernel() {
    __shared__ float arow[128];
    int i = blockIdx.x;
    int j = threadIdx.x;
    arow[j] = g_Ainv[i * 128 + j];
    __syncthreads();
    float s = 0.0f;
#pragma unroll 8
    for (int k = 0; k < 128; ++k) s += arow[k] * g_G[k * DIM + 128 + j];
    g_T[i * 128 + j] = s;
}

__global__ void kS_kernel() {
    __shared__ float bcol[128];
    int i = blockIdx.x;
    int j = threadIdx.x;
    bcol[j] = g_G[j * DIM + 128 + i];
    __syncthreads();
    float s = g_G[(128 + i) * DIM + 128 + j];
#pragma unroll 8
    for (int k = 0; k < 128; ++k) s -= bcol[k] * g_T[k * 128 + j];
    g_S[i * 128 + j] = s;
}

__global__ void kM12_kernel() {
    __shared__ float trow[128];
    int i = blockIdx.x;
    int j = threadIdx.x;
    trow[j] = g_T[i * 128 + j];
    __syncthreads();
    float s = 0.0f;
#pragma unroll 8
    for (int k = 0; k < 128; ++k) s += trow[k] * g_Sinv[k * 128 + j];
    g_M12[i * 128 + j] = -s;
}

__global__ void kM11_kernel() {
    __shared__ float m12row[128];
    int i = blockIdx.x;
    int j = threadIdx.x;
    m12row[j] = g_M12[i * 128 + j];
    __syncthreads();
    float s = g_Ainv[i * 128 + j];
#pragma unroll 8
    for (int k = 0; k < 128; ++k) s -= m12row[k] * g_T[j * 128 + k];
    g_M11[i * 128 + j] = s;
}

__global__ void assemble_kernel() {
    int i = blockIdx.x;
    int j = threadIdx.x;
    float v;
    if (i < 128) {
        v = (j < 128) ? g_M11[i * 128 + j] : g_M12[i * 128 + (j - 128)];
    } else {
        v = (j < 128) ? g_M12[j * 128 + (i - 128)] : g_Sinv[(i - 128) * 128 + (j - 128)];
    }
    g_Minv[i * DIM + j] = v;
}

// ---------------- 4) transpose dictionary -> g_Dt ------------------------------
__global__ void transpose_kernel(const float* __restrict__ dict) {
    __shared__ float t[32][33];
    int bx = blockIdx.x;
    int by = blockIdx.y;
    int x = bx * 32 + threadIdx.x;
#pragma unroll
    for (int r = 0; r < 32; r += 8) {
        int k = by * 32 + threadIdx.y + r;
        t[threadIdx.y + r][threadIdx.x] = dict[k * DIM + x];
    }
    __syncthreads();
#pragma unroll
    for (int r = 0; r < 32; r += 8) {
        int i = bx * 32 + threadIdx.y + r;
        g_Dt[i * NATOMS + by * 32 + threadIdx.x] = t[threadIdx.x][threadIdx.y + r];
    }
}

// ---------------- 5) W = Minv * Dt ---------------------------------------------
__global__ void w_kernel() {
    __shared__ float mrow[8][DIM];
    int j0 = blockIdx.x * 8;
    for (int t = threadIdx.x; t < 8 * DIM; t += 512) {
        mrow[t >> 8][t & 255] = g_Minv[(j0 + (t >> 8)) * DIM + (t & 255)];
    }
    __syncthreads();
    int k = threadIdx.x;
    float s[8];
#pragma unroll
    for (int r = 0; r < 8; ++r) s[r] = 0.0f;
    for (int i = 0; i < DIM; ++i) {
        float dv = g_Dt[i * NATOMS + k];
#pragma unroll
        for (int r = 0; r < 8; ++r) s[r] += mrow[r][i] * dv;
    }
#pragma unroll
    for (int r = 0; r < 8; ++r) g_W[(j0 + r) * NATOMS + k] = s[r];
}

// ---------------- 6a) X [k][m] fp32 -> Xt_hi/lo [m][k] bf16 split --------------
__global__ void xt_convert_kernel(const float* __restrict__ X) {
    __shared__ float t[32][33];
    int m0 = blockIdx.x * 32;
    int k0 = blockIdx.y * 32;
#pragma unroll
    for (int r = 0; r < 32; r += 8) {
        t[threadIdx.y + r][threadIdx.x] =
            X[(size_t)(k0 + threadIdx.y + r) * NCOLS + m0 + threadIdx.x];
    }
    __syncthreads();
#pragma unroll
    for (int r = 0; r < 32; r += 8) {
        int m = m0 + threadIdx.y + r;
        float v = t[threadIdx.x][threadIdx.y + r];
        __nv_bfloat16 h = __float2bfloat16(v);
        __nv_bfloat16 l = __float2bfloat16(v - __bfloat162float(h));
        size_t off = (size_t)m * DIM + k0 + threadIdx.x;
        g_Xt_hi[off] = h;
        g_Xt_lo[off] = l;
    }
}

// ---------------- 6b) W [k][n] fp32 -> Wt_hi/lo [n][k] bf16 split --------------
__global__ void wt_convert_kernel() {
    __shared__ float t[32][33];
    int n0 = blockIdx.x * 32;
    int k0 = blockIdx.y * 32;
#pragma unroll
    for (int r = 0; r < 32; r += 8) {
        t[threadIdx.y + r][threadIdx.x] =
            g_W[(k0 + threadIdx.y + r) * NATOMS + n0 + threadIdx.x];
    }
    __syncthreads();
#pragma unroll
    for (int r = 0; r < 32; r += 8) {
        int n = n0 + threadIdx.y + r;
        float v = t[threadIdx.x][threadIdx.y + r];
        __nv_bfloat16 h = __float2bfloat16(v);
        __nv_bfloat16 l = __float2bfloat16(v - __bfloat162float(h));
        size_t off = (size_t)n * DIM + k0 + threadIdx.x;
        g_Wt_hi[off] = h;
        g_Wt_lo[off] = l;
    }
}

// ---------------- 7) split-bf16 GEMM via mma.sync.m16n8k16 ---------------------
// out[m][n] = sum_k Xt[m][k] * Wt[n][k];  CTA tile 128m x 128n, BK=32, 2-stage
// cp.async pipeline. 8 warps (2m x 4n), warp tile 64m x 32n.
// SMEM rows padded to 80B (20 b32): lane addr gid*20+tig mod 32 hits all banks.
#define GBM 128
#define GBN 128
#define GBK 32
#define ROWB 80                     // padded row stride in bytes
#define OFF_AHI 0
#define OFF_ALO (128 * ROWB)        // 10240
#define OFF_BHI (2 * 128 * ROWB)    // 20480
#define OFF_BLO (3 * 128 * ROWB)    // 30720
#define STAGE_B (4 * 128 * ROWB)    // 40960
#define GSMEM_TOTAL (2 * STAGE_B)   // 81920

__global__ __launch_bounds__(256, 2) void mma_gemm_kernel(float* __restrict__ out) {
    extern __shared__ char smem[];
    const uint32_t sb = smem_u32(smem);
    const int tid = threadIdx.x;
    const int m0 = blockIdx.x * GBM;
    const int n0 = blockIdx.y * GBN;

    const int lane = tid & 31, warp = tid >> 5;
    const int gid = lane >> 2, tig = lane & 3;
    const int wm = (warp >> 2) * 64;    // 0 or 64
    const int wn = (warp & 3) * 32;     // 0,32,64,96

    float acc[4][4][4];
#pragma unroll
    for (int i = 0; i < 4; ++i)
#pragma unroll
        for (int j = 0; j < 4; ++j)
#pragma unroll
            for (int q = 0; q < 4; ++q) acc[i][j][q] = 0.0f;

    // ---- load mapping: 256 threads, each copies 2x16B per matrix per stage
    const int lrow = tid >> 1;                 // 0..127
    const int lc0 = (tid & 1) * 2;             // chunk 0 or 2 (of 4 x 16B)
    const __nv_bfloat16* gAh = g_Xt_hi + (size_t)(m0 + lrow) * DIM + lc0 * 8;
    const __nv_bfloat16* gAl = g_Xt_lo + (size_t)(m0 + lrow) * DIM + lc0 * 8;
    const __nv_bfloat16* gBh = g_Wt_hi + (size_t)(n0 + lrow) * DIM + lc0 * 8;
    const __nv_bfloat16* gBl = g_Wt_lo + (size_t)(n0 + lrow) * DIM + lc0 * 8;
    const uint32_t sRow = (uint32_t)(lrow * ROWB + lc0 * 16);

#define LOAD_STAGE(s, kc)                                                        \
    do {                                                                         \
        uint32_t _st = sb + (s) * STAGE_B + sRow;                                \
        int _ke = (kc) * GBK;                                                    \
        cp_async16(_st + OFF_AHI,      gAh + _ke);                               \
        cp_async16(_st + OFF_AHI + 16, gAh + _ke + 8);                           \
        cp_async16(_st + OFF_ALO,      gAl + _ke);                               \
        cp_async16(_st + OFF_ALO + 16, gAl + _ke + 8);                           \
        cp_async16(_st + OFF_BHI,      gBh + _ke);                               \
        cp_async16(_st + OFF_BHI + 16, gBh + _ke + 8);                           \
        cp_async16(_st + OFF_BLO,      gBl + _ke);                               \
        cp_async16(_st + OFF_BLO + 16, gBl + _ke + 8);                           \
    } while (0)

    LOAD_STAGE(0, 0);
    cp_commit();

    for (int kc = 0; kc < 8; ++kc) {
        const int s = kc & 1;
        if (kc < 7) {
            LOAD_STAGE(s ^ 1, kc + 1);
            cp_commit();
            cp_wait1();
        } else {
            cp_wait0();
        }
        __syncthreads();

        const uint32_t stb = sb + s * STAGE_B;
#pragma unroll
        for (int ks = 0; ks < 2; ++ks) {
            const uint32_t cb = (uint32_t)((ks * 8 + tig) * 4);   // frag col bytes
            // B fragments for all 4 n-tiles (hi + lo)
            uint32_t bh[4][2], bl[4][2];
#pragma unroll
            for (int tn = 0; tn < 4; ++tn) {
                uint32_t ro = stb + (uint32_t)((wn + tn * 8 + gid) * ROWB) + cb;
                bh[tn][0] = lds32(ro + OFF_BHI);
                bh[tn][1] = lds32(ro + OFF_BHI + 16);
                bl[tn][0] = lds32(ro + OFF_BLO);
                bl[tn][1] = lds32(ro + OFF_BLO + 16);
            }
#pragma unroll
            for (int tm = 0; tm < 4; ++tm) {
                uint32_t ro = stb + (uint32_t)((wm + tm * 16 + gid) * ROWB) + cb;
                uint32_t ah0 = lds32(ro + OFF_AHI);
                uint32_t ah1 = lds32(ro + OFF_AHI + 8 * ROWB);
                uint32_t ah2 = lds32(ro + OFF_AHI + 16);
                uint32_t ah3 = lds32(ro + OFF_AHI + 8 * ROWB + 16);
                uint32_t al0 = lds32(ro + OFF_ALO);
                uint32_t al1 = lds32(ro + OFF_ALO + 8 * ROWB);
                uint32_t al2 = lds32(ro + OFF_ALO + 16);
                uint32_t al3 = lds32(ro + OFF_ALO + 8 * ROWB + 16);
#pragma unroll
                for (int tn = 0; tn < 4; ++tn) {
                    mma16816(acc[tm][tn], ah0, ah1, ah2, ah3, bh[tn][0], bh[tn][1]);
                    mma16816(acc[tm][tn], ah0, ah1, ah2, ah3, bl[tn][0], bl[tn][1]);
                    mma16816(acc[tm][tn], al0, al1, al2, al3, bh[tn][0], bh[tn][1]);
                }
            }
        }
        __syncthreads();
    }

    // ---- epilogue: d0,d1 = (row gid, cols tig*2,+1); d2,d3 = row gid+8
#pragma unroll
    for (int tm = 0; tm < 4; ++tm) {
        int m = m0 + wm + tm * 16 + gid;
#pragma unroll
        for (int tn = 0; tn < 4; ++tn) {
            int n = n0 + wn + tn * 8 + tig * 2;
            float2 v0 = make_float2(acc[tm][tn][0], acc[tm][tn][1]);
            float2 v1 = make_float2(acc[tm][tn][2], acc[tm][tn][3]);
            *reinterpret_cast<float2*>(&out[(size_t)m * NATOMS + n]) = v0;
            *reinterpret_cast<float2*>(&out[(size_t)(m + 8) * NATOMS + n]) = v1;
        }
    }
}

// ---------------- launch --------------------------------------------------------
extern "C" void kernel_launch(void* const* d_in, const int* in_sizes, int n_in,
                              void* d_out, int out_size) {
    const float* z_e  = (const float*)d_in[0];
    const float* dict = (const float*)d_in[1];
    if (in_sizes[0] == NATOMS * DIM && in_sizes[1] == DIM * NCOLS) {
        dict = (const float*)d_in[0];
        z_e  = (const float*)d_in[1];
    }
    float* out = (float*)d_out;

    cudaFuncSetAttribute(mma_gemm_kernel, cudaFuncAttributeMaxDynamicSharedMemorySize,
                         GSMEM_TOTAL);

    // X conversion is independent of the W chain; issue it first
    xt_convert_kernel<<<dim3(NCOLS / 32, DIM / 32), dim3(32, 8)>>>(z_e);

    gram_kernel<<<32, 256>>>(dict);
    inv128_kernel<<<1, 1024>>>(0);
    kT_kernel<<<128, 128>>>();
    kS_kernel<<<128, 128>>>();
    inv128_kernel<<<1, 1024>>>(1);
    kM12_kernel<<<128, 128>>>();
    kM11_kernel<<<128, 128>>>();
    assemble_kernel<<<DIM, DIM>>>();
    transpose_kernel<<<dim3(8, 16), dim3(32, 8)>>>(dict);
    w_kernel<<<32, 512>>>();
    wt_convert_kernel<<<dim3(NATOMS / 32, DIM / 32), dim3(32, 8)>>>();

    mma_gemm_kernel<<<dim3(NCOLS / GBM, NATOMS / GBN), 256, GSMEM_TOTAL>>>(out);
}

// round 7
// speedup vs baseline: 1.3188x; 1.0554x over previous
#include <cuda_runtime.h>
#include <cuda_bf16.h>
#include <cstdint>

// Problem constants
#define DIM 256
#define NATOMS 512
#define NCOLS 65536

// ---------------- device scratch (no allocation allowed) ----------------
__device__ float g_G[DIM * DIM];        // Gram matrix G = D D^T  (256x256)
__device__ float g_Ainv[128 * 128];
__device__ float g_T[128 * 128];        // T = Ainv * B
__device__ float g_S[128 * 128];        // Schur complement
__device__ float g_Sinv[128 * 128];
__device__ float g_M12[128 * 128];
__device__ float g_Minv[DIM * DIM];     // G^{-1} (256x256)
__device__ float g_Dt[DIM * NATOMS];    // D (= dictionary^T), [256][512]
__device__ int   g_bar[8];              // software grid-barrier counters

// bf16 split operands (16-byte aligned for cp.async 16B)
__device__ __align__(16) __nv_bfloat16 g_Xt_hi[(size_t)NCOLS * DIM];  // [m][k]
__device__ __align__(16) __nv_bfloat16 g_Xt_lo[(size_t)NCOLS * DIM];
__device__ __align__(16) __nv_bfloat16 g_Wt_hi[NATOMS * DIM];         // [n][k]
__device__ __align__(16) __nv_bfloat16 g_Wt_lo[NATOMS * DIM];

// ================= helpers (family-portable PTX only) =================
__device__ __forceinline__ uint32_t smem_u32(const void* p) {
    uint32_t a;
    asm("{ .reg .u64 t; cvta.to.shared.u64 t, %1; cvt.u32.u64 %0, t; }" : "=r"(a) : "l"(p));
    return a;
}
__device__ __forceinline__ uint32_t lds32(uint32_t addr) {
    uint32_t v;
    asm volatile("ld.shared.b32 %0, [%1];" : "=r"(v) : "r"(addr));
    return v;
}
__device__ __forceinline__ void cp_async16(uint32_t smem_addr, const void* gptr) {
    asm volatile("cp.async.cg.shared.global [%0], [%1], 16;" :: "r"(smem_addr), "l"(gptr));
}
__device__ __forceinline__ void cp_commit() {
    asm volatile("cp.async.commit_group;" ::: "memory");
}
__device__ __forceinline__ void cp_wait1() {
    asm volatile("cp.async.wait_group 1;" ::: "memory");
}
__device__ __forceinline__ void cp_wait0() {
    asm volatile("cp.async.wait_group 0;" ::: "memory");
}
__device__ __forceinline__ void mma16816(float* d, uint32_t a0, uint32_t a1, uint32_t a2,
                                         uint32_t a3, uint32_t b0, uint32_t b1) {
    asm volatile(
        "mma.sync.aligned.m16n8k16.row.col.f32.bf16.bf16.f32 "
        "{%0,%1,%2,%3}, {%4,%5,%6,%7}, {%8,%9}, {%0,%1,%2,%3};"
        : "+f"(d[0]), "+f"(d[1]), "+f"(d[2]), "+f"(d[3])
        : "r"(a0), "r"(a1), "r"(a2), "r"(a3), "r"(b0), "r"(b1));
}

// ---------------- prep: transpose dictionary -> g_Dt + reset barriers ----------
__global__ void prep_kernel(const float* __restrict__ dict) {
    if (blockIdx.x == 0 && threadIdx.x == 0 && threadIdx.y == 0) {
#pragma unroll
        for (int s = 0; s < 8; ++s) g_bar[s] = 0;
    }
    __shared__ float t[32][33];
    int bx = blockIdx.x & 7;     // 8 tiles along i (DIM)
    int by = blockIdx.x >> 3;    // 16 tiles along k (NATOMS)
    int x = bx * 32 + threadIdx.x;
#pragma unroll
    for (int r = 0; r < 32; r += 8) {
        int k = by * 32 + threadIdx.y + r;
        t[threadIdx.y + r][threadIdx.x] = dict[k * DIM + x];
    }
    __syncthreads();
#pragma unroll
    for (int r = 0; r < 32; r += 8) {
        int i = bx * 32 + threadIdx.y + r;
        g_Dt[i * NATOMS + by * 32 + threadIdx.x] = t[threadIdx.x][threadIdx.y + r];
    }
}

// ---------------- X [k][m] fp32 -> Xt_hi/lo [m][k] bf16 split ------------------
__global__ void xt_convert_kernel(const float* __restrict__ X) {
    __shared__ float t[32][33];
    int m0 = blockIdx.x * 32;
    int k0 = blockIdx.y * 32;
#pragma unroll
    for (int r = 0; r < 32; r += 8) {
        t[threadIdx.y + r][threadIdx.x] =
            X[(size_t)(k0 + threadIdx.y + r) * NCOLS + m0 + threadIdx.x];
    }
    __syncthreads();
#pragma unroll
    for (int r = 0; r < 32; r += 8) {
        int m = m0 + threadIdx.y + r;
        float v = t[threadIdx.x][threadIdx.y + r];
        __nv_bfloat16 h = __float2bfloat16(v);
        __nv_bfloat16 l = __float2bfloat16(v - __bfloat162float(h));
        size_t off = (size_t)m * DIM + k0 + threadIdx.x;
        g_Xt_hi[off] = h;
        g_Xt_lo[off] = l;
    }
}

// ---------------- persistent chain kernel --------------------------------------
// 128 CTAs x 1024 threads, all resident (128 <= 148 SMs). Software grid barriers.
#define NBLK 128

__device__ __forceinline__ void grid_bar(int s) {
    __syncthreads();
    if (threadIdx.x == 0) {
        __threadfence();
        atomicAdd(&g_bar[s], 1);
        while (atomicAdd(&g_bar[s], 0) < NBLK) __nanosleep(64);
        __threadfence();
    }
    __syncthreads();
}

// 1024-thread register-resident Gauss-Jordan 128x128 inverse (verified R3 code).
__device__ void gj128(int which) {
    const float* src = (which == 0) ? g_G : g_S;
    float* dst       = (which == 0) ? g_Ainv : g_Sinv;
    int lds          = (which == 0) ? DIM : 128;

    __shared__ float sh_col[128];
    __shared__ float sh_row[128];
    int tid = threadIdx.x;
    int row = tid >> 3;
    int seg = (tid & 7) << 4;
    float a[16];
#pragma unroll
    for (int c = 0; c < 16; ++c) a[c] = src[row * lds + seg + c];

    for (int k = 0; k < 128; ++k) {
#pragma unroll
        for (int c = 0; c < 16; ++c)
            if (seg + c == k) sh_col[row] = a[c];
        __syncthreads();
        float p = 1.0f / sh_col[k];
        float f = sh_col[row];
        if (row == k) {
#pragma unroll
            for (int c = 0; c < 16; ++c) {
                int j = seg + c;
                float v = (j == k) ? p : a[c] * p;
                a[c] = v;
                sh_row[j] = v;
            }
        }
        __syncthreads();
        if (row != k) {
#pragma unroll
            for (int c = 0; c < 16; ++c) {
                int j = seg + c;
                a[c] = (j == k) ? (-f * p) : (a[c] - f * sh_row[j]);
            }
        }
        __syncthreads();
    }
#pragma unroll
    for (int c = 0; c < 16; ++c) dst[row * 128 + seg + c] = a[c];
}

__global__ __launch_bounds__(1024, 1) void persist_kernel(const float* __restrict__ dict) {
    const int tid = threadIdx.x;
    const int c = blockIdx.x;           // 0..127
    __shared__ float srow[128];
    __shared__ float sdcol[4][256];

    // ---- S0: gram. CTA c computes G rows {2c, 2c+1} over 256 threads (j=tid).
    if (tid < 256) {
        int j = tid;
        const float* d0 = dict + 2 * c;
        const float* d1 = dict + 2 * c + 1;
        const float* dj = dict + j;
        float s0 = 0.0f, s1 = 0.0f;
#pragma unroll 8
        for (int a = 0; a < NATOMS; ++a) {
            float v = dj[a * DIM];
            s0 += d0[a * DIM] * v;
            s1 += d1[a * DIM] * v;
        }
        g_G[(2 * c) * DIM + j] = s0;
        g_G[(2 * c + 1) * DIM + j] = s1;
    }
    grid_bar(0);

    // ---- S1: invert A11 (CTA 0 only)
    if (c == 0) gj128(0);
    grid_bar(1);

    // ---- S2: T[c][j] = sum_k Ainv[c][k] * G[k][128+j]
    if (tid < 128) srow[tid] = g_Ainv[c * 128 + tid];
    __syncthreads();
    if (tid < 128) {
        int j = tid;
        float s = 0.0f;
#pragma unroll 8
        for (int k = 0; k < 128; ++k) s += srow[k] * g_G[k * DIM + 128 + j];
        g_T[c * 128 + j] = s;
    }
    grid_bar(2);

    // ---- S3: S[c][j] = G[128+c][128+j] - sum_k G[k][128+c] * T[k][j]
    __syncthreads();
    if (tid < 128) srow[tid] = g_G[tid * DIM + 128 + c];
    __syncthreads();
    if (tid < 128) {
        int j = tid;
        float s = g_G[(128 + c) * DIM + 128 + j];
#pragma unroll 8
        for (int k = 0; k < 128; ++k) s -= srow[k] * g_T[k * 128 + j];
        g_S[c * 128 + j] = s;
    }
    grid_bar(3);

    // ---- S4: invert S (CTA 0 only)
    if (c == 0) gj128(1);
    grid_bar(4);

    // ---- S5: U = T*Sinv; M12 = -U; write M12/M21/Sinv quadrants of Minv
    __syncthreads();
    if (tid < 128) srow[tid] = g_T[c * 128 + tid];
    __syncthreads();
    if (tid < 128) {
        int j = tid;
        float u = 0.0f;
#pragma unroll 8
        for (int k = 0; k < 128; ++k) u += srow[k] * g_Sinv[k * 128 + j];
        g_M12[c * 128 + j] = -u;
        g_Minv[c * DIM + 128 + j] = -u;
        g_Minv[(128 + j) * DIM + c] = -u;
        g_Minv[(128 + c) * DIM + 128 + j] = g_Sinv[c * 128 + j];
    }
    grid_bar(5);

    // ---- S6: M11[c][j] = Ainv[c][j] - sum_k M12[c][k] * T[j][k]
    __syncthreads();
    if (tid < 128) srow[tid] = g_M12[c * 128 + tid];
    __syncthreads();
    if (tid < 128) {
        int j = tid;
        float s = g_Ainv[c * 128 + j];
#pragma unroll 8
        for (int k = 0; k < 128; ++k) s -= srow[k] * g_T[j * 128 + k];
        g_Minv[c * DIM + j] = s;
    }
    grid_bar(6);

    // ---- S7: W split. CTA c handles atoms n0=4c..4c+3.
    // Wt[n][i] = sum_j Minv[j][i] * Dt[j][n]   (Minv symmetric)
    {
        int q = tid >> 8;           // 0..3
        int i = tid & 255;          // 0..255
        sdcol[q][i] = g_Dt[i * NATOMS + 4 * c + q];   // Dt[j=i][n0+q]
        __syncthreads();
        float acc = 0.0f;
#pragma unroll 8
        for (int j = 0; j < DIM; ++j) acc += g_Minv[j * DIM + i] * sdcol[q][j];
        __nv_bfloat16 h = __float2bfloat16(acc);
        __nv_bfloat16 l = __float2bfloat16(acc - __bfloat162float(h));
        g_Wt_hi[(4 * c + q) * DIM + i] = h;
        g_Wt_lo[(4 * c + q) * DIM + i] = l;
    }
}

// ---------------- split-bf16 GEMM via mma.sync.m16n8k16 ------------------------
#define GBM 128
#define GBN 128
#define GBK 32
#define ROWB 80
#define OFF_AHI 0
#define OFF_ALO (128 * ROWB)
#define OFF_BHI (2 * 128 * ROWB)
#define OFF_BLO (3 * 128 * ROWB)
#define STAGE_B (4 * 128 * ROWB)
#define GSMEM_TOTAL (2 * STAGE_B)

__global__ __launch_bounds__(256, 2) void mma_gemm_kernel(float* __restrict__ out) {
    extern __shared__ char smem[];
    const uint32_t sb = smem_u32(smem);
    const int tid = threadIdx.x;
    const int m0 = blockIdx.x * GBM;
    const int n0 = blockIdx.y * GBN;

    const int lane = tid & 31, warp = tid >> 5;
    const int gid = lane >> 2, tig = lane & 3;
    const int wm = (warp >> 2) * 64;
    const int wn = (warp & 3) * 32;

    float acc[4][4][4];
#pragma unroll
    for (int i = 0; i < 4; ++i)
#pragma unroll
        for (int j = 0; j < 4; ++j)
#pragma unroll
            for (int q = 0; q < 4; ++q) acc[i][j][q] = 0.0f;

    const int lrow = tid >> 1;
    const int lc0 = (tid & 1) * 2;
    const __nv_bfloat16* gAh = g_Xt_hi + (size_t)(m0 + lrow) * DIM + lc0 * 8;
    const __nv_bfloat16* gAl = g_Xt_lo + (size_t)(m0 + lrow) * DIM + lc0 * 8;
    const __nv_bfloat16* gBh = g_Wt_hi + (size_t)(n0 + lrow) * DIM + lc0 * 8;
    const __nv_bfloat16* gBl = g_Wt_lo + (size_t)(n0 + lrow) * DIM + lc0 * 8;
    const uint32_t sRow = (uint32_t)(lrow * ROWB + lc0 * 16);

#define LOAD_STAGE(s, kc)                                                        \
    do {                                                                         \
        uint32_t _st = sb + (s) * STAGE_B + sRow;                                \
        int _ke = (kc) * GBK;                                                    \
        cp_async16(_st + OFF_AHI,      gAh + _ke);                               \
        cp_async16(_st + OFF_AHI + 16, gAh + _ke + 8);                           \
        cp_async16(_st + OFF_ALO,      gAl + _ke);                               \
        cp_async16(_st + OFF_ALO + 16, gAl + _ke + 8);                           \
        cp_async16(_st + OFF_BHI,      gBh + _ke);                               \
        cp_async16(_st + OFF_BHI + 16, gBh + _ke + 8);                           \
        cp_async16(_st + OFF_BLO,      gBl + _ke);                               \
        cp_async16(_st + OFF_BLO + 16, gBl + _ke + 8);                           \
    } while (0)

    LOAD_STAGE(0, 0);
    cp_commit();

    for (int kc = 0; kc < 8; ++kc) {
        const int s = kc & 1;
        if (kc < 7) {
            LOAD_STAGE(s ^ 1, kc + 1);
            cp_commit();
            cp_wait1();
        } else {
            cp_wait0();
        }
        __syncthreads();

        const uint32_t stb = sb + s * STAGE_B;
#pragma unroll
        for (int ks = 0; ks < 2; ++ks) {
            const uint32_t cb = (uint32_t)((ks * 8 + tig) * 4);
            uint32_t bh[4][2], bl[4][2];
#pragma unroll
            for (int tn = 0; tn < 4; ++tn) {
                uint32_t ro = stb + (uint32_t)((wn + tn * 8 + gid) * ROWB) + cb;
                bh[tn][0] = lds32(ro + OFF_BHI);
                bh[tn][1] = lds32(ro + OFF_BHI + 16);
                bl[tn][0] = lds32(ro + OFF_BLO);
                bl[tn][1] = lds32(ro + OFF_BLO + 16);
            }
#pragma unroll
            for (int tm = 0; tm < 4; ++tm) {
                uint32_t ro = stb + (uint32_t)((wm + tm * 16 + gid) * ROWB) + cb;
                uint32_t ah0 = lds32(ro + OFF_AHI);
                uint32_t ah1 = lds32(ro + OFF_AHI + 8 * ROWB);
                uint32_t ah2 = lds32(ro + OFF_AHI + 16);
                uint32_t ah3 = lds32(ro + OFF_AHI + 8 * ROWB + 16);
                uint32_t al0 = lds32(ro + OFF_ALO);
                uint32_t al1 = lds32(ro + OFF_ALO + 8 * ROWB);
                uint32_t al2 = lds32(ro + OFF_ALO + 16);
                uint32_t al3 = lds32(ro + OFF_ALO + 8 * ROWB + 16);
                // interleave split-MMAs: same-acc distance = 4 (breaks RAW chains)
#pragma unroll
                for (int tn = 0; tn < 4; ++tn)
                    mma16816(acc[tm][tn], ah0, ah1, ah2, ah3, bh[tn][0], bh[tn][1]);
#pragma unroll
                for (int tn = 0; tn < 4; ++tn)
                    mma16816(acc[tm][tn], ah0, ah1, ah2, ah3, bl[tn][0], bl[tn][1]);
#pragma unroll
                for (int tn = 0; tn < 4; ++tn)
                    mma16816(acc[tm][tn], al0, al1, al2, al3, bh[tn][0], bh[tn][1]);
            }
        }
        __syncthreads();
    }

#pragma unroll
    for (int tm = 0; tm < 4; ++tm) {
        int m = m0 + wm + tm * 16 + gid;
#pragma unroll
        for (int tn = 0; tn < 4; ++tn) {
            int n = n0 + wn + tn * 8 + tig * 2;
            float2 v0 = make_float2(acc[tm][tn][0], acc[tm][tn][1]);
            float2 v1 = make_float2(acc[tm][tn][2], acc[tm][tn][3]);
            *reinterpret_cast<float2*>(&out[(size_t)m * NATOMS + n]) = v0;
            *reinterpret_cast<float2*>(&out[(size_t)(m + 8) * NATOMS + n]) = v1;
        }
    }
}

// ---------------- launch --------------------------------------------------------
extern "C" void kernel_launch(void* const* d_in, const int* in_sizes, int n_in,
                              void* d_out, int out_size) {
    const float* z_e  = (const float*)d_in[0];
    const float* dict = (const float*)d_in[1];
    if (in_sizes[0] == NATOMS * DIM && in_sizes[1] == DIM * NCOLS) {
        dict = (const float*)d_in[0];
        z_e  = (const float*)d_in[1];
    }
    float* out = (float*)d_out;

    cudaFuncSetAttribute(mma_gemm_kernel, cudaFuncAttributeMaxDynamicSharedMemorySize,
                         GSMEM_TOTAL);

    // launch idx 0..3; ncu empirically captures idx 3 -> the GEMM.
    xt_convert_kernel<<<dim3(NCOLS / 32, DIM / 32), dim3(32, 8)>>>(z_e);   // idx 0
    prep_kernel<<<128, dim3(32, 8)>>>(dict);                               // idx 1
    persist_kernel<<<NBLK, 1024>>>(dict);                                  // idx 2
    mma_gemm_kernel<<<dim3(NCOLS / GBM, NATOMS / GBN), 256, GSMEM_TOTAL>>>(out);  // idx 3
}